// round 16
// baseline (speedup 1.0000x reference)
#include <cuda_runtime.h>
#include <cuda_fp16.h>
#include <math.h>
#include <stdint.h>

#define T_TOK   2048
#define DM      512
#define E_EXP   64
#define TOPK    8
#define H_GATE  1024
#define H_EXP   2048
#define NPAIR   (T_TOK*TOPK)
#define NPART   256       // route blocks (8 tokens each)
#define KGATE   1536
#define KGATE2  3072      // logits GEMM K: [h_hi | h_hi | h_lo]
#define NL      128       // logits GEMM N (64 experts zero-padded)
#define MAXBLK  192

// ---------------- scratch (device globals) ----------------------------------
static __device__ float  g_topkw[T_TOK * TOPK];
static __device__ float  g_part[NPART][E_EXP];
static __device__ int    g_count[E_EXP];
static __device__ int    g_list_t[E_EXP * T_TOK];
static __device__ int    g_list_p[E_EXP * T_TOK];
static __device__ int2   g_btab[MAXBLK + 1];
static __device__ int    g_nblk;
static __device__ __half g_x16[(size_t)T_TOK * DM];
static __device__ __half g_gx[(size_t)T_TOK * KGATE];
static __device__ __half g_gw[(size_t)KGATE * H_GATE];
static __device__ __half g_gx2[(size_t)T_TOK * KGATE2];      // [h_hi|h_hi|h_lo]
static __device__ __half g_gw2c[(size_t)KGATE2 * NL];
static __device__ float  g_b2pad[NL];
static __device__ float  g_logits[(size_t)T_TOK * NL];
static __device__ __half g_w1h[(size_t)E_EXP * DM * H_EXP];
static __device__ __half g_w2h[(size_t)E_EXP * H_EXP * DM];
static __device__ __half g_hidden16[(size_t)NPAIR * H_EXP];
static __device__ float  g_ybuf[(size_t)NPAIR * DM];

// ---------------- helpers ----------------------------------------------------
__device__ __forceinline__ uint32_t smem_u32(const void* p) {
    uint32_t a;
    asm("{ .reg .u64 t; cvta.to.shared.u64 t, %1; cvt.u32.u64 %0, t; }" : "=r"(a) : "l"(p));
    return a;
}
__device__ __forceinline__ uint32_t packh(float lo, float hi) {
    uint32_t r;
    asm("cvt.rn.f16x2.f32 %0, %1, %2;" : "=r"(r) : "f"(hi), "f"(lo));
    return r;
}
__device__ __forceinline__ void cp16(uint32_t dst, const void* src, int srcsize) {
    asm volatile("cp.async.cg.shared.global [%0], [%1], 16, %2;"
                 :: "r"(dst), "l"(src), "r"(srcsize) : "memory");
}
__device__ __forceinline__ void cp_commit() {
    asm volatile("cp.async.commit_group;" ::: "memory");
}
__device__ __forceinline__ void ldsm4(uint32_t* r, uint32_t addr) {
    asm volatile("ldmatrix.sync.aligned.m8n8.x4.shared.b16 {%0,%1,%2,%3}, [%4];"
                 : "=r"(r[0]), "=r"(r[1]), "=r"(r[2]), "=r"(r[3]) : "r"(addr));
}
__device__ __forceinline__ void ldsm4t(uint32_t* r, uint32_t addr) {
    asm volatile("ldmatrix.sync.aligned.m8n8.x4.trans.shared.b16 {%0,%1,%2,%3}, [%4];"
                 : "=r"(r[0]), "=r"(r[1]), "=r"(r[2]), "=r"(r[3]) : "r"(addr));
}
__device__ __forceinline__ void mma_f16(float* c, const uint32_t* a, uint32_t b0, uint32_t b1) {
    asm volatile(
        "mma.sync.aligned.m16n8k16.row.col.f32.f16.f16.f32 "
        "{%0,%1,%2,%3}, {%4,%5,%6,%7}, {%8,%9}, {%0,%1,%2,%3};"
        : "+f"(c[0]), "+f"(c[1]), "+f"(c[2]), "+f"(c[3])
        : "r"(a[0]), "r"(a[1]), "r"(a[2]), "r"(a[3]), "r"(b0), "r"(b1));
}

// ---------------- fused fp32 -> fp16 bulk convert (w1 then w2) ---------------
__global__ void cvt16_w(const float4* __restrict__ w1, uint4* __restrict__ o1,
                        const float4* __restrict__ w2, uint4* __restrict__ o2,
                        int n8each)
{
    int stride = gridDim.x * blockDim.x;
    int total = 2 * n8each;
    for (int i = blockIdx.x * blockDim.x + threadIdx.x; i < total; i += stride) {
        const float4* in; uint4* out; int j;
        if (i < n8each) { in = w1; out = o1; j = i; }
        else            { in = w2; out = o2; j = i - n8each; }
        float4 v0 = __ldg(&in[2 * j]);
        float4 v1 = __ldg(&in[2 * j + 1]);
        uint4 o;
        o.x = packh(v0.x, v0.y); o.y = packh(v0.z, v0.w);
        o.z = packh(v1.x, v1.y); o.w = packh(v1.z, v1.w);
        out[j] = o;
    }
}

// ---- fused split: [0,512) x, [512,1024) gw1, [1024,1088) gw2+b2pad ---------
__global__ void split_xgw(const float4* __restrict__ x, uint2* __restrict__ x16,
                          uint2* __restrict__ gx,
                          const float4* __restrict__ w, uint2* __restrict__ gw,
                          const float4* __restrict__ w2, uint2* __restrict__ gw2c,
                          const float* __restrict__ b2)
{
    if (blockIdx.x == 0 && threadIdx.x < E_EXP) g_count[threadIdx.x] = 0;
    if (blockIdx.x < 512) {
        const int n4 = T_TOK * DM / 4;
        int stride = 512 * blockDim.x;
        for (int i = blockIdx.x * blockDim.x + threadIdx.x; i < n4; i += stride) {
            float4 v = __ldg(&x[i]);
            __half hx = __float2half_rn(v.x), hy = __float2half_rn(v.y);
            __half hz = __float2half_rn(v.z), hw = __float2half_rn(v.w);
            uint2 h, l;
            h.x = packh(__half2float(hx), __half2float(hy));
            h.y = packh(__half2float(hz), __half2float(hw));
            l.x = packh(v.x - __half2float(hx), v.y - __half2float(hy));
            l.y = packh(v.z - __half2float(hz), v.w - __half2float(hw));
            x16[i] = h;
            int t  = i >> 7;
            int c4 = i & 127;
            uint2* row = gx + (size_t)t * 384;
            row[c4]       = h;
            row[c4 + 128] = h;
            row[c4 + 256] = l;
        }
    } else if (blockIdx.x < 1024) {
        const int n4 = DM * H_GATE / 4;
        int stride = 512 * blockDim.x;
        for (int i = (blockIdx.x - 512) * blockDim.x + threadIdx.x; i < n4; i += stride) {
            float4 v = __ldg(&w[i]);
            __half hx = __float2half_rn(v.x), hy = __float2half_rn(v.y);
            __half hz = __float2half_rn(v.z), hw = __float2half_rn(v.w);
            uint2 h, l;
            h.x = packh(__half2float(hx), __half2float(hy));
            h.y = packh(__half2float(hz), __half2float(hw));
            l.x = packh(v.x - __half2float(hx), v.y - __half2float(hy));
            l.y = packh(v.z - __half2float(hz), v.w - __half2float(hw));
            int row = i >> 8;
            int c4  = i & 255;
            gw[(size_t)row * 256 + c4]          = h;
            gw[(size_t)(row + 512) * 256 + c4]  = l;
            gw[(size_t)(row + 1024) * 256 + c4] = h;
        }
    } else {
        if (blockIdx.x == 1024 && threadIdx.x < NL)
            g_b2pad[threadIdx.x] = (threadIdx.x < E_EXP) ? b2[threadIdx.x] : 0.f;
        int i = (blockIdx.x - 1024) * blockDim.x + threadIdx.x;   // 0..16383
        int k  = i >> 4;
        int e4 = i & 15;
        float4 v = __ldg(&w2[i]);
        __half hx = __float2half_rn(v.x), hy = __float2half_rn(v.y);
        __half hz = __float2half_rn(v.z), hw = __float2half_rn(v.w);
        uint2 h, l, z;
        h.x = packh(__half2float(hx), __half2float(hy));
        h.y = packh(__half2float(hz), __half2float(hw));
        l.x = packh(v.x - __half2float(hx), v.y - __half2float(hy));
        l.y = packh(v.z - __half2float(hz), v.w - __half2float(hw));
        z.x = 0u; z.y = 0u;
        gw2c[(size_t)k * 32 + e4]                = h;
        gw2c[(size_t)(k + 1024) * 32 + e4]       = l;
        gw2c[(size_t)(k + 2048) * 32 + e4]       = h;
        gw2c[(size_t)k * 32 + e4 + 16]           = z;
        gw2c[(size_t)(k + 1024) * 32 + e4 + 16]  = z;
        gw2c[(size_t)(k + 2048) * 32 + e4 + 16]  = z;
    }
}

// ---------------- block table build ------------------------------------------
__global__ void build_btab()
{
    __shared__ int off[E_EXP];
    const int e = threadIdx.x;
    int nb = (g_count[e] + 127) >> 7;
    off[e] = nb;
    __syncthreads();
    if (e == 0) {
        int s = 0;
        for (int i = 0; i < E_EXP; i++) { int t = off[i]; off[i] = s; s += t; }
        g_nblk = s;
    }
    __syncthreads();
    int o = off[e];
    for (int b = 0; b < nb; b++) g_btab[o + b] = make_int2(e, b * 128);
}

// ---------------- all-fp16 grouped GEMM: cp.async + ldmatrix + HMMA ----------
// HSPLIT: epilogue writes [h_hi|h_hi|h_lo] fp16 triple (C is __half*, ldc=3072)
template<typename OT, int ACT, int SCALE, int HSPLIT>
__global__ __launch_bounds__(256, 2)
void mma_gemm16(const __half* __restrict__ A, int lda, int K,
                const __half* __restrict__ Bbase, size_t strideB, int N,
                const float* __restrict__ biasBase, int strideBias,
                OT* __restrict__ C, int ldc,
                const int* __restrict__ rowlist, const int* __restrict__ outlist,
                const int* __restrict__ cnts, int Mfixed,
                const int2* __restrict__ btab)
{
    int e, m0;
    if (btab) {
        if ((int)blockIdx.x >= g_nblk) return;
        int2 be = btab[blockIdx.x];
        e = be.x; m0 = be.y;
    } else {
        e = blockIdx.z; m0 = blockIdx.x * 128;
    }
    const int M = cnts ? cnts[e] : Mfixed;
    if (m0 >= M) return;
    const int n0 = blockIdx.y * 128;

    extern __shared__ char sm[];
    const uint32_t smBytes = smem_u32(sm);

    const int tid  = threadIdx.x;
    const int wid  = tid >> 5;
    const int lane = tid & 31;
    const int wy   = wid & 3;
    const int wx   = wid >> 2;
    const int g    = lane >> 2;
    const int tig  = lane & 3;

    const int* rl = rowlist ? rowlist + e * T_TOK : nullptr;
    const int* ol = outlist ? outlist + e * T_TOK : nullptr;

    const __half* aSrc[4]; int aSz[4];
    uint32_t aOff0, bOff0;
    const __half* bSrc0;
    {
        int ar = tid >> 3, s = tid & 7;
        aOff0 = (uint32_t)(ar * 128 + 16 * (s ^ (ar & 7)));
        #pragma unroll
        for (int j = 0; j < 4; j++) {
            int gm = m0 + ar + j * 32;
            if (gm < M) { aSrc[j] = A + (size_t)(rl ? rl[gm] : gm) * lda + s * 8; aSz[j] = 16; }
            else        { aSrc[j] = A;                                            aSz[j] = 0;  }
        }
        int bk = tid >> 4, s2 = tid & 15;
        bOff0 = 16384u + (uint32_t)(bk * 256 + 16 * (s2 ^ (bk & 7)));
        bSrc0 = Bbase + (size_t)e * strideB + (size_t)bk * N + n0 + s2 * 8;
    }

    const int NC = K / 64;
    const size_t bStep = (size_t)64 * N;

    #define ISSUE(cc) do { \
        uint32_t st = smBytes + (uint32_t)((cc) % 3) * 32768u; \
        _Pragma("unroll") \
        for (int j = 0; j < 4; j++) \
            cp16(st + aOff0 + (uint32_t)j * 4096u, aSrc[j] + (size_t)(cc) * 64, aSz[j]); \
        _Pragma("unroll") \
        for (int j = 0; j < 4; j++) \
            cp16(st + bOff0 + (uint32_t)j * 4096u, bSrc0 + (size_t)j * 16 * N + (size_t)(cc) * bStep, 16); \
        cp_commit(); \
    } while (0)

    ISSUE(0);
    if (NC > 1) ISSUE(1);

    float acc[2][8][4];
    #pragma unroll
    for (int fm = 0; fm < 2; fm++)
        #pragma unroll
        for (int fn = 0; fn < 8; fn++)
            #pragma unroll
            for (int q = 0; q < 4; q++) acc[fm][fn][q] = 0.f;

    const int mlane = wy * 32 + (lane & 15);
    const int aksel = (lane >> 4) & 1;
    const int bklan = lane & 15;
    const int bnsel = ((lane >> 4) & 1) * 8;

    for (int c = 0; c < NC; c++) {
        if (c + 1 < NC) asm volatile("cp.async.wait_group 1;" ::: "memory");
        else            asm volatile("cp.async.wait_group 0;" ::: "memory");
        __syncthreads();

        if (c + 2 < NC) ISSUE(c + 2);

        const uint32_t stA = smBytes + (uint32_t)(c % 3) * 32768u;
        const uint32_t stB = stA + 16384u;

        #pragma unroll
        for (int ks = 0; ks < 4; ks++) {
            const int aseg = ks * 2 + aksel;
            uint32_t a0[4], a1[4];
            {
                int m = mlane;
                ldsm4(a0, stA + m * 128 + 16 * (aseg ^ (m & 7)));
                m = mlane + 16;
                ldsm4(a1, stA + m * 128 + 16 * (aseg ^ (m & 7)));
            }
            const int kk = ks * 16 + bklan;
            const uint32_t brow = stB + kk * 256;
            const int ksw = kk & 7;
            #pragma unroll
            for (int nb = 0; nb < 4; nb++) {
                int nseg = (wx * 64 + nb * 16 + bnsel) >> 3;
                uint32_t bb[4];
                ldsm4t(bb, brow + 16 * (nseg ^ ksw));
                mma_f16(acc[0][2 * nb],     a0, bb[0], bb[1]);
                mma_f16(acc[1][2 * nb],     a1, bb[0], bb[1]);
                mma_f16(acc[0][2 * nb + 1], a0, bb[2], bb[3]);
                mma_f16(acc[1][2 * nb + 1], a1, bb[2], bb[3]);
            }
        }
    }
    #undef ISSUE

    // ---- epilogue -----------------------------------------------------------
    const float* bias = biasBase ? biasBase + (size_t)e * strideBias + n0 : nullptr;
    #pragma unroll
    for (int fm = 0; fm < 2; fm++) {
        int r0 = m0 + wy * 32 + fm * 16 + g;
        #pragma unroll
        for (int half = 0; half < 2; half++) {
            int row = r0 + half * 8;
            if (row >= M) continue;
            int orow = ol ? ol[row] : row;
            float wgt = 1.f;
            if (SCALE) wgt = g_topkw[orow];
            OT* cp = C + (size_t)orow * ldc + n0;
            #pragma unroll
            for (int fn = 0; fn < 8; fn++) {
                int col = wx * 64 + fn * 8 + 2 * tig;
                float v0 = acc[fm][fn][half * 2 + 0] + (bias ? bias[col]     : 0.f);
                float v1 = acc[fm][fn][half * 2 + 1] + (bias ? bias[col + 1] : 0.f);
                if (ACT == 1) { v0 = fmaxf(v0, 0.f); v1 = fmaxf(v1, 0.f); }
                if (ACT == 2) {
                    v0 = 0.5f * v0 * (1.f + erff(v0 * 0.70710678118654752f));
                    v1 = 0.5f * v1 * (1.f + erff(v1 * 0.70710678118654752f));
                }
                if (SCALE) { v0 *= wgt; v1 *= wgt; }
                if (HSPLIT) {
                    __half h0 = __float2half_rn(v0), h1 = __float2half_rn(v1);
                    uint32_t hiw = packh(__half2float(h0), __half2float(h1));
                    uint32_t low = packh(v0 - __half2float(h0), v1 - __half2float(h1));
                    __half* hp = (__half*)cp + col;
                    *(uint32_t*)(hp)        = hiw;
                    *(uint32_t*)(hp + 1024) = hiw;
                    *(uint32_t*)(hp + 2048) = low;
                } else if (sizeof(OT) == 4) {
                    *(float2*)((float*)cp + col) = make_float2(v0, v1);
                } else {
                    *(uint32_t*)((__half*)cp + col) = packh(v0, v1);
                }
            }
        }
    }
}

// ---------------- routing: softmax + top-8 + usage partials ------------------
__global__ __launch_bounds__(256)
void route_kernel(const float* __restrict__ logits)
{
    __shared__ float sp[8][E_EXP];
    const int warp = threadIdx.x >> 5;
    const int lane = threadIdx.x & 31;
    const int t = blockIdx.x * 8 + warp;

    float a0 = logits[(size_t)t * NL + lane];
    float a1 = logits[(size_t)t * NL + lane + 32];

    float mx = fmaxf(a0, a1);
    #pragma unroll
    for (int s = 16; s; s >>= 1) mx = fmaxf(mx, __shfl_xor_sync(~0u, mx, s));
    float p0 = expf(a0 - mx), p1 = expf(a1 - mx);
    float sum = p0 + p1;
    #pragma unroll
    for (int s = 16; s; s >>= 1) sum += __shfl_xor_sync(~0u, sum, s);
    p0 /= sum; p1 /= sum;
    sp[warp][lane]      = p0;
    sp[warp][lane + 32] = p1;

    float v0 = p0, v1 = p1;
    float selw[TOPK]; int seli[TOPK];
    #pragma unroll
    for (int k = 0; k < TOPK; k++) {
        float v; int idx;
        if (v0 >= v1) { v = v0; idx = lane; } else { v = v1; idx = lane + 32; }
        #pragma unroll
        for (int s = 16; s; s >>= 1) {
            float ov = __shfl_xor_sync(~0u, v, s);
            int   oi = __shfl_xor_sync(~0u, idx, s);
            if (ov > v || (ov == v && oi < idx)) { v = ov; idx = oi; }
        }
        selw[k] = v; seli[k] = idx;
        if (idx == lane) v0 = -1.f;
        else if (idx == lane + 32) v1 = -1.f;
    }

    if (lane == 0) {
        float s8 = 0.f;
        #pragma unroll
        for (int k = 0; k < TOPK; k++) s8 += selw[k];
        float inv = 1.f / s8;
        #pragma unroll
        for (int k = 0; k < TOPK; k++) {
            int ee = seli[k];
            g_topkw[t * TOPK + k] = selw[k] * inv;
            int pos = atomicAdd(&g_count[ee], 1);
            g_list_t[ee * T_TOK + pos] = t;
            g_list_p[ee * T_TOK + pos] = t * TOPK + k;
        }
    }

    // usage partials: this block's 8 tokens, per expert (deterministic)
    __syncthreads();
    if (threadIdx.x < E_EXP) {
        float s = 0.f;
        #pragma unroll
        for (int w = 0; w < 8; w++) s += sp[w][threadIdx.x];
        g_part[blockIdx.x][threadIdx.x] = s;
    }
}

// ---------------- load-balance loss -------------------------------------------
__global__ void lb_final(float* __restrict__ out, int out_size)
{
    __shared__ float red[E_EXP];
    const int e = threadIdx.x;
    float s = 0.f;
    for (int b = 0; b < NPART; b++) s += g_part[b][e];
    float u = s / (float)T_TOK - 1.f / (float)E_EXP;
    red[e] = u * u; __syncthreads();
    for (int st = 32; st > 0; st >>= 1) { if (e < st) red[e] += red[e + st]; __syncthreads(); }
    if (e == 0 && out_size > T_TOK * DM)
        out[T_TOK * DM] = 0.01f * red[0] / (float)E_EXP;
}

// ---------------- combine: plain 8-row sum ------------------------------------
__global__ __launch_bounds__(128)
void combine_kernel(float* __restrict__ out)
{
    const int t = blockIdx.x;
    const int d4 = threadIdx.x;
    const float4* yb = (const float4*)g_ybuf;
    float4 a = make_float4(0.f, 0.f, 0.f, 0.f);
    #pragma unroll
    for (int k = 0; k < TOPK; k++) {
        float4 y = yb[(size_t)(t * TOPK + k) * (DM / 4) + d4];
        a.x += y.x; a.y += y.y; a.z += y.z; a.w += y.w;
    }
    ((float4*)out)[(size_t)t * (DM / 4) + d4] = a;
}

// ---------------- launch ------------------------------------------------------
extern "C" void kernel_launch(void* const* d_in, const int* in_sizes, int n_in,
                              void* d_out, int out_size)
{
    const float* x   = (const float*)d_in[0];
    const float* gw1 = (const float*)d_in[1];
    const float* gb1 = (const float*)d_in[2];
    const float* gw2 = (const float*)d_in[3];
    const float* gb2 = (const float*)d_in[4];
    const float* ew1 = (const float*)d_in[5];
    const float* eb1 = (const float*)d_in[6];
    const float* ew2 = (const float*)d_in[7];
    const float* eb2 = (const float*)d_in[8];
    float* out = (float*)d_out;

    float *pybuf, *pb2pad, *plogits;
    __half *phid, *px16, *pgx, *pgw, *pgx2, *pgw2c, *pw1h, *pw2h;
    int *pcnt, *plt, *plp;
    int2* pbtab;
    cudaGetSymbolAddress((void**)&phid,   g_hidden16);
    cudaGetSymbolAddress((void**)&px16,   g_x16);
    cudaGetSymbolAddress((void**)&pgx,    g_gx);
    cudaGetSymbolAddress((void**)&pgw,    g_gw);
    cudaGetSymbolAddress((void**)&pgx2,   g_gx2);
    cudaGetSymbolAddress((void**)&pgw2c,  g_gw2c);
    cudaGetSymbolAddress((void**)&pb2pad, g_b2pad);
    cudaGetSymbolAddress((void**)&plogits,g_logits);
    cudaGetSymbolAddress((void**)&pw1h,   g_w1h);
    cudaGetSymbolAddress((void**)&pw2h,   g_w2h);
    cudaGetSymbolAddress((void**)&pybuf,  g_ybuf);
    cudaGetSymbolAddress((void**)&pcnt,   g_count);
    cudaGetSymbolAddress((void**)&plt,    g_list_t);
    cudaGetSymbolAddress((void**)&plp,    g_list_p);
    cudaGetSymbolAddress((void**)&pbtab,  g_btab);

    const int SMEM_DYN = 3 * 32768;   // 96 KB
    cudaFuncSetAttribute((const void*)mma_gemm16<__half, 1, 0, 1>,
                         cudaFuncAttributeMaxDynamicSharedMemorySize, SMEM_DYN);
    cudaFuncSetAttribute((const void*)mma_gemm16<float, 0, 0, 0>,
                         cudaFuncAttributeMaxDynamicSharedMemorySize, SMEM_DYN);
    cudaFuncSetAttribute((const void*)mma_gemm16<__half, 2, 0, 0>,
                         cudaFuncAttributeMaxDynamicSharedMemorySize, SMEM_DYN);
    cudaFuncSetAttribute((const void*)mma_gemm16<float, 0, 1, 0>,
                         cudaFuncAttributeMaxDynamicSharedMemorySize, SMEM_DYN);

    // fused weight conversion (w1 + w2)
    {
        int n8w = (E_EXP * DM * H_EXP) / 8;
        cvt16_w<<<8192, 256>>>((const float4*)ew1, (uint4*)pw1h,
                               (const float4*)ew2, (uint4*)pw2h, n8w);
    }

    // fused splits (x, gw1, gw2+b2pad; zeroes counts)
    split_xgw<<<1088, 256>>>((const float4*)x, (uint2*)px16, (uint2*)pgx,
                             (const float4*)gw1, (uint2*)pgw,
                             (const float4*)gw2, (uint2*)pgw2c, gb2);

    // gate layer 1: h = relu([x_hi|x_hi|x_lo] @ [w_hi;w_lo;w_hi] + b1)
    // epilogue writes [h_hi|h_hi|h_lo] directly (split_h fused)
    mma_gemm16<__half, 1, 0, 1><<<dim3(T_TOK/128, H_GATE/128, 1), 256, SMEM_DYN>>>(
        pgx, KGATE, KGATE, pgw, 0, H_GATE, gb1, 0,
        pgx2, KGATE2, nullptr, nullptr, nullptr, T_TOK, nullptr);

    // logits: error-compensated GEMM (K=3072, N=128 padded)
    mma_gemm16<float, 0, 0, 0><<<dim3(T_TOK/128, NL/128, 1), 256, SMEM_DYN>>>(
        pgx2, KGATE2, KGATE2, pgw2c, 0, NL, pb2pad, 0,
        plogits, NL, nullptr, nullptr, nullptr, T_TOK, nullptr);

    // softmax + top-8 + routing lists + usage partials
    route_kernel<<<T_TOK / 8, 256>>>(plogits);

    build_btab<<<1, E_EXP>>>();
    lb_final<<<1, E_EXP>>>(out, out_size);

    // expert GEMM 1 (compacted): hidden16 = gelu(x16[list] @ w1h[e] + eb1)
    mma_gemm16<__half, 2, 0, 0><<<dim3(MAXBLK, H_EXP/128, 1), 256, SMEM_DYN>>>(
        px16, DM, DM, pw1h, (size_t)DM * H_EXP, H_EXP, eb1, H_EXP,
        phid, H_EXP, plt, plp, pcnt, 0, pbtab);

    // expert GEMM 2 (compacted, scaled): ybuf = topkw * (hidden16 @ w2h + eb2)
    mma_gemm16<float, 0, 1, 0><<<dim3(MAXBLK, DM/128, 1), 256, SMEM_DYN>>>(
        phid, H_EXP, H_EXP, pw2h, (size_t)H_EXP * DM, DM, eb2, DM,
        pybuf, DM, plp, plp, pcnt, 0, pbtab);

    combine_kernel<<<T_TOK, 128>>>(out);
}

// round 17
// speedup vs baseline: 1.0760x; 1.0760x over previous
#include <cuda_runtime.h>
#include <cuda_fp16.h>
#include <math.h>
#include <stdint.h>

#define T_TOK   2048
#define DM      512
#define E_EXP   64
#define TOPK    8
#define H_GATE  1024
#define H_EXP   2048
#define NPAIR   (T_TOK*TOPK)
#define NPART   256
#define KGATE   1536
#define KGATE2  3072      // logits GEMM K: [h_hi | h_hi | h_lo]
#define NL      128       // logits GEMM N (64 experts zero-padded)
#define SPLK    8         // logits split-K segments
#define MAXBLK  192

// ---------------- scratch (device globals) ----------------------------------
static __device__ float  g_topkw[T_TOK * TOPK];
static __device__ float  g_part[NPART][E_EXP];
static __device__ int    g_count[E_EXP];
static __device__ int    g_list_t[E_EXP * T_TOK];
static __device__ int    g_list_p[E_EXP * T_TOK];
static __device__ int2   g_btab[MAXBLK + 1];
static __device__ int    g_nblk;
static __device__ __half g_x16[(size_t)T_TOK * DM];
static __device__ __half g_gx[(size_t)T_TOK * KGATE];
static __device__ __half g_gw[(size_t)KGATE * H_GATE];
static __device__ __half g_gx2[(size_t)T_TOK * KGATE2];      // [h_hi|h_hi|h_lo]
static __device__ __half g_gw2c[(size_t)KGATE2 * NL];
static __device__ float  g_b2pad[NL];
static __device__ float  g_logits[SPLK][(size_t)T_TOK * NL]; // 8 MiB
static __device__ __half g_w1h[(size_t)E_EXP * DM * H_EXP];
static __device__ __half g_w2h[(size_t)E_EXP * H_EXP * DM];
static __device__ __half g_hidden16[(size_t)NPAIR * H_EXP];
static __device__ float  g_ybuf[(size_t)NPAIR * DM];

// ---------------- helpers ----------------------------------------------------
__device__ __forceinline__ uint32_t smem_u32(const void* p) {
    uint32_t a;
    asm("{ .reg .u64 t; cvta.to.shared.u64 t, %1; cvt.u32.u64 %0, t; }" : "=r"(a) : "l"(p));
    return a;
}
__device__ __forceinline__ uint32_t packh(float lo, float hi) {
    uint32_t r;
    asm("cvt.rn.f16x2.f32 %0, %1, %2;" : "=r"(r) : "f"(hi), "f"(lo));
    return r;
}
__device__ __forceinline__ void cp16(uint32_t dst, const void* src, int srcsize) {
    asm volatile("cp.async.cg.shared.global [%0], [%1], 16, %2;"
                 :: "r"(dst), "l"(src), "r"(srcsize) : "memory");
}
__device__ __forceinline__ void cp_commit() {
    asm volatile("cp.async.commit_group;" ::: "memory");
}
__device__ __forceinline__ void ldsm4(uint32_t* r, uint32_t addr) {
    asm volatile("ldmatrix.sync.aligned.m8n8.x4.shared.b16 {%0,%1,%2,%3}, [%4];"
                 : "=r"(r[0]), "=r"(r[1]), "=r"(r[2]), "=r"(r[3]) : "r"(addr));
}
__device__ __forceinline__ void ldsm4t(uint32_t* r, uint32_t addr) {
    asm volatile("ldmatrix.sync.aligned.m8n8.x4.trans.shared.b16 {%0,%1,%2,%3}, [%4];"
                 : "=r"(r[0]), "=r"(r[1]), "=r"(r[2]), "=r"(r[3]) : "r"(addr));
}
__device__ __forceinline__ void mma_f16(float* c, const uint32_t* a, uint32_t b0, uint32_t b1) {
    asm volatile(
        "mma.sync.aligned.m16n8k16.row.col.f32.f16.f16.f32 "
        "{%0,%1,%2,%3}, {%4,%5,%6,%7}, {%8,%9}, {%0,%1,%2,%3};"
        : "+f"(c[0]), "+f"(c[1]), "+f"(c[2]), "+f"(c[3])
        : "r"(a[0]), "r"(a[1]), "r"(a[2]), "r"(a[3]), "r"(b0), "r"(b1));
}

// ---------------- fused fp32 -> fp16 bulk convert (w1 then w2) ---------------
__global__ void cvt16_w(const float4* __restrict__ w1, uint4* __restrict__ o1,
                        const float4* __restrict__ w2, uint4* __restrict__ o2,
                        int n8each)
{
    int stride = gridDim.x * blockDim.x;
    int total = 2 * n8each;
    for (int i = blockIdx.x * blockDim.x + threadIdx.x; i < total; i += stride) {
        const float4* in; uint4* out; int j;
        if (i < n8each) { in = w1; out = o1; j = i; }
        else            { in = w2; out = o2; j = i - n8each; }
        float4 v0 = __ldg(&in[2 * j]);
        float4 v1 = __ldg(&in[2 * j + 1]);
        uint4 o;
        o.x = packh(v0.x, v0.y); o.y = packh(v0.z, v0.w);
        o.z = packh(v1.x, v1.y); o.w = packh(v1.z, v1.w);
        out[j] = o;
    }
}

// ---- fused split: [0,512) x, [512,1024) gw1, [1024,1088) gw2+b2pad ---------
__global__ void split_xgw(const float4* __restrict__ x, uint2* __restrict__ x16,
                          uint2* __restrict__ gx,
                          const float4* __restrict__ w, uint2* __restrict__ gw,
                          const float4* __restrict__ w2, uint2* __restrict__ gw2c,
                          const float* __restrict__ b2)
{
    if (blockIdx.x == 0 && threadIdx.x < E_EXP) g_count[threadIdx.x] = 0;
    if (blockIdx.x < 512) {
        const int n4 = T_TOK * DM / 4;
        int stride = 512 * blockDim.x;
        for (int i = blockIdx.x * blockDim.x + threadIdx.x; i < n4; i += stride) {
            float4 v = __ldg(&x[i]);
            __half hx = __float2half_rn(v.x), hy = __float2half_rn(v.y);
            __half hz = __float2half_rn(v.z), hw = __float2half_rn(v.w);
            uint2 h, l;
            h.x = packh(__half2float(hx), __half2float(hy));
            h.y = packh(__half2float(hz), __half2float(hw));
            l.x = packh(v.x - __half2float(hx), v.y - __half2float(hy));
            l.y = packh(v.z - __half2float(hz), v.w - __half2float(hw));
            x16[i] = h;
            int t  = i >> 7;
            int c4 = i & 127;
            uint2* row = gx + (size_t)t * 384;
            row[c4]       = h;
            row[c4 + 128] = h;
            row[c4 + 256] = l;
        }
    } else if (blockIdx.x < 1024) {
        const int n4 = DM * H_GATE / 4;
        int stride = 512 * blockDim.x;
        for (int i = (blockIdx.x - 512) * blockDim.x + threadIdx.x; i < n4; i += stride) {
            float4 v = __ldg(&w[i]);
            __half hx = __float2half_rn(v.x), hy = __float2half_rn(v.y);
            __half hz = __float2half_rn(v.z), hw = __float2half_rn(v.w);
            uint2 h, l;
            h.x = packh(__half2float(hx), __half2float(hy));
            h.y = packh(__half2float(hz), __half2float(hw));
            l.x = packh(v.x - __half2float(hx), v.y - __half2float(hy));
            l.y = packh(v.z - __half2float(hz), v.w - __half2float(hw));
            int row = i >> 8;
            int c4  = i & 255;
            gw[(size_t)row * 256 + c4]          = h;
            gw[(size_t)(row + 512) * 256 + c4]  = l;
            gw[(size_t)(row + 1024) * 256 + c4] = h;
        }
    } else {
        if (blockIdx.x == 1024 && threadIdx.x < NL)
            g_b2pad[threadIdx.x] = (threadIdx.x < E_EXP) ? b2[threadIdx.x] : 0.f;
        int i = (blockIdx.x - 1024) * blockDim.x + threadIdx.x;
        int k  = i >> 4;
        int e4 = i & 15;
        float4 v = __ldg(&w2[i]);
        __half hx = __float2half_rn(v.x), hy = __float2half_rn(v.y);
        __half hz = __float2half_rn(v.z), hw = __float2half_rn(v.w);
        uint2 h, l, z;
        h.x = packh(__half2float(hx), __half2float(hy));
        h.y = packh(__half2float(hz), __half2float(hw));
        l.x = packh(v.x - __half2float(hx), v.y - __half2float(hy));
        l.y = packh(v.z - __half2float(hz), v.w - __half2float(hw));
        z.x = 0u; z.y = 0u;
        gw2c[(size_t)k * 32 + e4]                = h;
        gw2c[(size_t)(k + 1024) * 32 + e4]       = l;
        gw2c[(size_t)(k + 2048) * 32 + e4]       = h;
        gw2c[(size_t)k * 32 + e4 + 16]           = z;
        gw2c[(size_t)(k + 1024) * 32 + e4 + 16]  = z;
        gw2c[(size_t)(k + 2048) * 32 + e4 + 16]  = z;
    }
}

// ---------------- block table build ------------------------------------------
__global__ void build_btab()
{
    __shared__ int off[E_EXP];
    const int e = threadIdx.x;
    int nb = (g_count[e] + 127) >> 7;
    off[e] = nb;
    __syncthreads();
    if (e == 0) {
        int s = 0;
        for (int i = 0; i < E_EXP; i++) { int t = off[i]; off[i] = s; s += t; }
        g_nblk = s;
    }
    __syncthreads();
    int o = off[e];
    for (int b = 0; b < nb; b++) g_btab[o + b] = make_int2(e, b * 128);
}

// ---------------- all-fp16 grouped GEMM: cp.async + ldmatrix + HMMA ----------
// HSPLIT: epilogue writes [h_hi|h_hi|h_lo]. SPLITK: blockIdx.z = K-segment;
// B segment via e*strideB, A offset seg*K, C offset seg*T_TOK*ldc, bias seg 0 only.
template<typename OT, int ACT, int SCALE, int HSPLIT, int SPLITK>
__global__ __launch_bounds__(256, 2)
void mma_gemm16(const __half* __restrict__ A, int lda, int K,
                const __half* __restrict__ Bbase, size_t strideB, int N,
                const float* __restrict__ biasBase, int strideBias,
                OT* __restrict__ C, int ldc,
                const int* __restrict__ rowlist, const int* __restrict__ outlist,
                const int* __restrict__ cnts, int Mfixed,
                const int2* __restrict__ btab)
{
    int e, m0;
    if (btab) {
        if ((int)blockIdx.x >= g_nblk) return;
        int2 be = btab[blockIdx.x];
        e = be.x; m0 = be.y;
    } else {
        e = blockIdx.z; m0 = blockIdx.x * 128;
    }
    const int M = cnts ? cnts[e] : Mfixed;
    if (m0 >= M) return;
    const int n0 = blockIdx.y * 128;

    if (SPLITK) {
        A += (size_t)e * K;                    // segment offset within rows
        C += (size_t)e * T_TOK * ldc;          // partial output buffer
    }

    extern __shared__ char sm[];
    const uint32_t smBytes = smem_u32(sm);

    const int tid  = threadIdx.x;
    const int wid  = tid >> 5;
    const int lane = tid & 31;
    const int wy   = wid & 3;
    const int wx   = wid >> 2;
    const int g    = lane >> 2;
    const int tig  = lane & 3;

    const int* rl = rowlist ? rowlist + e * T_TOK : nullptr;
    const int* ol = outlist ? outlist + e * T_TOK : nullptr;

    const __half* aSrc[4]; int aSz[4];
    uint32_t aOff0, bOff0;
    const __half* bSrc0;
    {
        int ar = tid >> 3, s = tid & 7;
        aOff0 = (uint32_t)(ar * 128 + 16 * (s ^ (ar & 7)));
        #pragma unroll
        for (int j = 0; j < 4; j++) {
            int gm = m0 + ar + j * 32;
            if (gm < M) { aSrc[j] = A + (size_t)(rl ? rl[gm] : gm) * lda + s * 8; aSz[j] = 16; }
            else        { aSrc[j] = A;                                            aSz[j] = 0;  }
        }
        int bk = tid >> 4, s2 = tid & 15;
        bOff0 = 16384u + (uint32_t)(bk * 256 + 16 * (s2 ^ (bk & 7)));
        bSrc0 = Bbase + (size_t)e * strideB + (size_t)bk * N + n0 + s2 * 8;
    }

    const int NC = K / 64;
    const size_t bStep = (size_t)64 * N;

    #define ISSUE(cc) do { \
        uint32_t st = smBytes + (uint32_t)((cc) % 3) * 32768u; \
        _Pragma("unroll") \
        for (int j = 0; j < 4; j++) \
            cp16(st + aOff0 + (uint32_t)j * 4096u, aSrc[j] + (size_t)(cc) * 64, aSz[j]); \
        _Pragma("unroll") \
        for (int j = 0; j < 4; j++) \
            cp16(st + bOff0 + (uint32_t)j * 4096u, bSrc0 + (size_t)j * 16 * N + (size_t)(cc) * bStep, 16); \
        cp_commit(); \
    } while (0)

    ISSUE(0);
    if (NC > 1) ISSUE(1);

    float acc[2][8][4];
    #pragma unroll
    for (int fm = 0; fm < 2; fm++)
        #pragma unroll
        for (int fn = 0; fn < 8; fn++)
            #pragma unroll
            for (int q = 0; q < 4; q++) acc[fm][fn][q] = 0.f;

    const int mlane = wy * 32 + (lane & 15);
    const int aksel = (lane >> 4) & 1;
    const int bklan = lane & 15;
    const int bnsel = ((lane >> 4) & 1) * 8;

    for (int c = 0; c < NC; c++) {
        if (c + 1 < NC) asm volatile("cp.async.wait_group 1;" ::: "memory");
        else            asm volatile("cp.async.wait_group 0;" ::: "memory");
        __syncthreads();

        if (c + 2 < NC) ISSUE(c + 2);

        const uint32_t stA = smBytes + (uint32_t)(c % 3) * 32768u;
        const uint32_t stB = stA + 16384u;

        #pragma unroll
        for (int ks = 0; ks < 4; ks++) {
            const int aseg = ks * 2 + aksel;
            uint32_t a0[4], a1[4];
            {
                int m = mlane;
                ldsm4(a0, stA + m * 128 + 16 * (aseg ^ (m & 7)));
                m = mlane + 16;
                ldsm4(a1, stA + m * 128 + 16 * (aseg ^ (m & 7)));
            }
            const int kk = ks * 16 + bklan;
            const uint32_t brow = stB + kk * 256;
            const int ksw = kk & 7;
            #pragma unroll
            for (int nb = 0; nb < 4; nb++) {
                int nseg = (wx * 64 + nb * 16 + bnsel) >> 3;
                uint32_t bb[4];
                ldsm4t(bb, brow + 16 * (nseg ^ ksw));
                mma_f16(acc[0][2 * nb],     a0, bb[0], bb[1]);
                mma_f16(acc[1][2 * nb],     a1, bb[0], bb[1]);
                mma_f16(acc[0][2 * nb + 1], a0, bb[2], bb[3]);
                mma_f16(acc[1][2 * nb + 1], a1, bb[2], bb[3]);
            }
        }
    }
    #undef ISSUE

    // ---- epilogue -----------------------------------------------------------
    const bool useBias = biasBase && (!SPLITK || e == 0);
    const float* bias = useBias ? biasBase + (SPLITK ? 0 : (size_t)e * strideBias) + n0 : nullptr;
    #pragma unroll
    for (int fm = 0; fm < 2; fm++) {
        int r0 = m0 + wy * 32 + fm * 16 + g;
        #pragma unroll
        for (int half = 0; half < 2; half++) {
            int row = r0 + half * 8;
            if (row >= M) continue;
            int orow = ol ? ol[row] : row;
            float wgt = 1.f;
            if (SCALE) wgt = g_topkw[orow];
            OT* cp = C + (size_t)orow * ldc + n0;
            #pragma unroll
            for (int fn = 0; fn < 8; fn++) {
                int col = wx * 64 + fn * 8 + 2 * tig;
                float v0 = acc[fm][fn][half * 2 + 0] + (bias ? bias[col]     : 0.f);
                float v1 = acc[fm][fn][half * 2 + 1] + (bias ? bias[col + 1] : 0.f);
                if (ACT == 1) { v0 = fmaxf(v0, 0.f); v1 = fmaxf(v1, 0.f); }
                if (ACT == 2) {
                    v0 = 0.5f * v0 * (1.f + erff(v0 * 0.70710678118654752f));
                    v1 = 0.5f * v1 * (1.f + erff(v1 * 0.70710678118654752f));
                }
                if (SCALE) { v0 *= wgt; v1 *= wgt; }
                if (HSPLIT) {
                    __half h0 = __float2half_rn(v0), h1 = __float2half_rn(v1);
                    uint32_t hiw = packh(__half2float(h0), __half2float(h1));
                    uint32_t low = packh(v0 - __half2float(h0), v1 - __half2float(h1));
                    __half* hp = (__half*)cp + col;
                    *(uint32_t*)(hp)        = hiw;
                    *(uint32_t*)(hp + 1024) = hiw;
                    *(uint32_t*)(hp + 2048) = low;
                } else if (sizeof(OT) == 4) {
                    *(float2*)((float*)cp + col) = make_float2(v0, v1);
                } else {
                    *(uint32_t*)((__half*)cp + col) = packh(v0, v1);
                }
            }
        }
    }
}

// ---------------- routing: sum split-K logits + softmax + top-8 + usage ------
__global__ __launch_bounds__(256)
void route_kernel()
{
    __shared__ float sp[8][E_EXP];
    const int warp = threadIdx.x >> 5;
    const int lane = threadIdx.x & 31;
    const int t = blockIdx.x * 8 + warp;

    float a0 = 0.f, a1 = 0.f;
    #pragma unroll
    for (int s = 0; s < SPLK; s++) {
        a0 += g_logits[s][(size_t)t * NL + lane];
        a1 += g_logits[s][(size_t)t * NL + lane + 32];
    }

    float mx = fmaxf(a0, a1);
    #pragma unroll
    for (int s = 16; s; s >>= 1) mx = fmaxf(mx, __shfl_xor_sync(~0u, mx, s));
    float p0 = expf(a0 - mx), p1 = expf(a1 - mx);
    float sum = p0 + p1;
    #pragma unroll
    for (int s = 16; s; s >>= 1) sum += __shfl_xor_sync(~0u, sum, s);
    p0 /= sum; p1 /= sum;
    sp[warp][lane]      = p0;
    sp[warp][lane + 32] = p1;

    float v0 = p0, v1 = p1;
    float selw[TOPK]; int seli[TOPK];
    #pragma unroll
    for (int k = 0; k < TOPK; k++) {
        float v; int idx;
        if (v0 >= v1) { v = v0; idx = lane; } else { v = v1; idx = lane + 32; }
        #pragma unroll
        for (int s = 16; s; s >>= 1) {
            float ov = __shfl_xor_sync(~0u, v, s);
            int   oi = __shfl_xor_sync(~0u, idx, s);
            if (ov > v || (ov == v && oi < idx)) { v = ov; idx = oi; }
        }
        selw[k] = v; seli[k] = idx;
        if (idx == lane) v0 = -1.f;
        else if (idx == lane + 32) v1 = -1.f;
    }

    if (lane == 0) {
        float s8 = 0.f;
        #pragma unroll
        for (int k = 0; k < TOPK; k++) s8 += selw[k];
        float inv = 1.f / s8;
        #pragma unroll
        for (int k = 0; k < TOPK; k++) {
            int ee = seli[k];
            g_topkw[t * TOPK + k] = selw[k] * inv;
            int pos = atomicAdd(&g_count[ee], 1);
            g_list_t[ee * T_TOK + pos] = t;
            g_list_p[ee * T_TOK + pos] = t * TOPK + k;
        }
    }

    __syncthreads();
    if (threadIdx.x < E_EXP) {
        float s = 0.f;
        #pragma unroll
        for (int w = 0; w < 8; w++) s += sp[w][threadIdx.x];
        g_part[blockIdx.x][threadIdx.x] = s;
    }
}

// ---------------- load-balance loss -------------------------------------------
__global__ void lb_final(float* __restrict__ out, int out_size)
{
    __shared__ float red[E_EXP];
    const int e = threadIdx.x;
    float s = 0.f;
    for (int b = 0; b < NPART; b++) s += g_part[b][e];
    float u = s / (float)T_TOK - 1.f / (float)E_EXP;
    red[e] = u * u; __syncthreads();
    for (int st = 32; st > 0; st >>= 1) { if (e < st) red[e] += red[e + st]; __syncthreads(); }
    if (e == 0 && out_size > T_TOK * DM)
        out[T_TOK * DM] = 0.01f * red[0] / (float)E_EXP;
}

// ---------------- combine: plain 8-row sum ------------------------------------
__global__ __launch_bounds__(128)
void combine_kernel(float* __restrict__ out)
{
    const int t = blockIdx.x;
    const int d4 = threadIdx.x;
    const float4* yb = (const float4*)g_ybuf;
    float4 a = make_float4(0.f, 0.f, 0.f, 0.f);
    #pragma unroll
    for (int k = 0; k < TOPK; k++) {
        float4 y = yb[(size_t)(t * TOPK + k) * (DM / 4) + d4];
        a.x += y.x; a.y += y.y; a.z += y.z; a.w += y.w;
    }
    ((float4*)out)[(size_t)t * (DM / 4) + d4] = a;
}

// ---------------- launch ------------------------------------------------------
extern "C" void kernel_launch(void* const* d_in, const int* in_sizes, int n_in,
                              void* d_out, int out_size)
{
    const float* x   = (const float*)d_in[0];
    const float* gw1 = (const float*)d_in[1];
    const float* gb1 = (const float*)d_in[2];
    const float* gw2 = (const float*)d_in[3];
    const float* gb2 = (const float*)d_in[4];
    const float* ew1 = (const float*)d_in[5];
    const float* eb1 = (const float*)d_in[6];
    const float* ew2 = (const float*)d_in[7];
    const float* eb2 = (const float*)d_in[8];
    float* out = (float*)d_out;

    float *pybuf, *pb2pad, *plogits;
    __half *phid, *px16, *pgx, *pgw, *pgx2, *pgw2c, *pw1h, *pw2h;
    int *pcnt, *plt, *plp;
    int2* pbtab;
    cudaGetSymbolAddress((void**)&phid,   g_hidden16);
    cudaGetSymbolAddress((void**)&px16,   g_x16);
    cudaGetSymbolAddress((void**)&pgx,    g_gx);
    cudaGetSymbolAddress((void**)&pgw,    g_gw);
    cudaGetSymbolAddress((void**)&pgx2,   g_gx2);
    cudaGetSymbolAddress((void**)&pgw2c,  g_gw2c);
    cudaGetSymbolAddress((void**)&pb2pad, g_b2pad);
    cudaGetSymbolAddress((void**)&plogits,g_logits);
    cudaGetSymbolAddress((void**)&pw1h,   g_w1h);
    cudaGetSymbolAddress((void**)&pw2h,   g_w2h);
    cudaGetSymbolAddress((void**)&pybuf,  g_ybuf);
    cudaGetSymbolAddress((void**)&pcnt,   g_count);
    cudaGetSymbolAddress((void**)&plt,    g_list_t);
    cudaGetSymbolAddress((void**)&plp,    g_list_p);
    cudaGetSymbolAddress((void**)&pbtab,  g_btab);

    const int SMEM_DYN = 3 * 32768;   // 96 KB
    cudaFuncSetAttribute((const void*)mma_gemm16<__half, 1, 0, 1, 0>,
                         cudaFuncAttributeMaxDynamicSharedMemorySize, SMEM_DYN);
    cudaFuncSetAttribute((const void*)mma_gemm16<float, 0, 0, 0, SPLK>,
                         cudaFuncAttributeMaxDynamicSharedMemorySize, SMEM_DYN);
    cudaFuncSetAttribute((const void*)mma_gemm16<__half, 2, 0, 0, 0>,
                         cudaFuncAttributeMaxDynamicSharedMemorySize, SMEM_DYN);
    cudaFuncSetAttribute((const void*)mma_gemm16<float, 0, 1, 0, 0>,
                         cudaFuncAttributeMaxDynamicSharedMemorySize, SMEM_DYN);

    // fused weight conversion (w1 + w2)
    {
        int n8w = (E_EXP * DM * H_EXP) / 8;
        cvt16_w<<<8192, 256>>>((const float4*)ew1, (uint4*)pw1h,
                               (const float4*)ew2, (uint4*)pw2h, n8w);
    }

    // fused splits (x, gw1, gw2+b2pad; zeroes counts)
    split_xgw<<<1088, 256>>>((const float4*)x, (uint2*)px16, (uint2*)pgx,
                             (const float4*)gw1, (uint2*)pgw,
                             (const float4*)gw2, (uint2*)pgw2c, gb2);

    // gate layer 1: h = relu([x_hi|x_hi|x_lo] @ [w_hi;w_lo;w_hi] + b1)
    // epilogue writes [h_hi|h_hi|h_lo] directly
    mma_gemm16<__half, 1, 0, 1, 0><<<dim3(T_TOK/128, H_GATE/128, 1), 256, SMEM_DYN>>>(
        pgx, KGATE, KGATE, pgw, 0, H_GATE, gb1, 0,
        pgx2, KGATE2, nullptr, nullptr, nullptr, T_TOK, nullptr);

    // logits: error-compensated split-K GEMM (8 segments x K=384, N=128)
    mma_gemm16<float, 0, 0, 0, SPLK><<<dim3(T_TOK/128, 1, SPLK), 256, SMEM_DYN>>>(
        pgx2, KGATE2, KGATE2 / SPLK, pgw2c, (size_t)(KGATE2 / SPLK) * NL, NL,
        pb2pad, 0,
        plogits, NL, nullptr, nullptr, nullptr, T_TOK, nullptr);

    // sum partials + softmax + top-8 + routing lists + usage partials
    route_kernel<<<T_TOK / 8, 256>>>();

    build_btab<<<1, E_EXP>>>();
    lb_final<<<1, E_EXP>>>(out, out_size);

    // expert GEMM 1 (compacted): hidden16 = gelu(x16[list] @ w1h[e] + eb1)
    mma_gemm16<__half, 2, 0, 0, 0><<<dim3(MAXBLK, H_EXP/128, 1), 256, SMEM_DYN>>>(
        px16, DM, DM, pw1h, (size_t)DM * H_EXP, H_EXP, eb1, H_EXP,
        phid, H_EXP, plt, plp, pcnt, 0, pbtab);

    // expert GEMM 2 (compacted, scaled): ybuf = topkw * (hidden16 @ w2h + eb2)
    mma_gemm16<float, 0, 1, 0, 0><<<dim3(MAXBLK, DM/128, 1), 256, SMEM_DYN>>>(
        phid, H_EXP, H_EXP, pw2h, (size_t)H_EXP * DM, DM, eb2, DM,
        pybuf, DM, plp, plp, pcnt, 0, pbtab);

    combine_kernel<<<T_TOK, 128>>>(out);
}